// round 7
// baseline (speedup 1.0000x reference)
#include <cuda_runtime.h>
#include <cstdint>

// FPS + gather, bit-exact vs JAX/XLA (distance = fma(dz,dz, fma(dx,dx, rn(dy*dy)))).
// B=8, N=131072, S=4096.
//
// R6: last-arriver sync. Each CTA publishes (payload v4 + tagged release key),
// then atom.add.acq_rel on a per-batch counter; the CTA seeing old==r*16+15 is
// last: it alone reads the 16 slots, reduces, publishes ONE result record.
// Others poll only that record (32-lane broadcast, 1 line/batch, batches on
// distinct LTS slices via 2048B alignment). No slot polling, no fences,
// winner coords carried in payloads (own-slice L1-hit fetch, pre-publish).
// Compute loop frozen (rel_err 0.0).

#define NB 8
#define NP 131072
#define NS 4096
#define CPB 16                 // CTAs per batch
#define NT 512                 // threads per CTA
#define ROUNDS (NS - 1)
#define PPC (NP / CPB)         // 8192 points per CTA
#define CHUNK 4                // 4 float4 per coord per thread = 16 pts/thread

__device__ float g_x[NB * NP];
__device__ float g_y[NB * NP];
__device__ float g_z[NB * NP];

struct __align__(2048) BSync {
    unsigned long long slotkey[2][CPB];   // [parity][cta] value|tag|idx
    float4             slotpay[2][CPB];   // [parity][cta] x,y,z,v
    unsigned long long reskey[2];         // [parity]
    float4             respay[2];         // [parity] x,y,z,v
    unsigned           cnt;               // monotonic arrivals
    unsigned           pad[9];
};
__device__ BSync g_sync[NB];

__global__ void fps_prep_kernel(const float* __restrict__ pts) {
    if (blockIdx.x == 0 && threadIdx.x < NB) {
        g_sync[threadIdx.x].cnt = 0u;
        g_sync[threadIdx.x].reskey[0] = 0ull;   // tag 0 never matches r+1
        g_sync[threadIdx.x].reskey[1] = 0ull;
    }
    int i = blockIdx.x * blockDim.x + threadIdx.x;
    int stride = gridDim.x * blockDim.x;
    for (; i < NB * NP; i += stride) {
        g_x[i] = pts[3 * i + 0];
        g_y[i] = pts[3 * i + 1];
        g_z[i] = pts[3 * i + 2];
    }
}

__global__ void __launch_bounds__(NT, 1) fps_main_kernel(float* __restrict__ out) {
    const int b    = blockIdx.x / CPB;
    const int c    = blockIdx.x % CPB;
    const int tid  = threadIdx.x;
    const int lane = tid & 31;
    const int wid  = tid >> 5;
    const int base = c * PPC;
    BSync* __restrict__ S = &g_sync[b];

    const float4* __restrict__ x4 = (const float4*)(g_x + b * NP + base);
    const float4* __restrict__ y4 = (const float4*)(g_y + b * NP + base);
    const float4* __restrict__ z4 = (const float4*)(g_z + b * NP + base);

    float md[CHUNK * 4];
#pragma unroll
    for (int i = 0; i < CHUNK * 4; ++i) md[i] = 1e10f;   // BIG

    __shared__ float s_v[NT / 32];
    __shared__ int   s_i[NT / 32];
    __shared__ float s_win[3];

    // selection 0 is always index 0
    float lx = g_x[b * NP + 0];
    float ly = g_y[b * NP + 0];
    float lz = g_z[b * NP + 0];

    if (c == 0 && tid == 0) {
        out[(b * NS + 0) * 3 + 0] = lx;
        out[(b * NS + 0) * 3 + 1] = ly;
        out[(b * NS + 0) * 3 + 2] = lz;
    }

    for (int r = 0; r < ROUNDS; ++r) {
        float bestv = -1.0f;
        int   besti = 0x7fffffff;

#pragma unroll
        for (int j = 0; j < CHUNK; ++j) {
            const int e = j * NT + tid;
            float4 X = x4[e];
            float4 Y = y4[e];
            float4 Z = z4[e];
            float xv[4] = {X.x, X.y, X.z, X.w};
            float yv[4] = {Y.x, Y.y, Y.z, Y.w};
            float zv[4] = {Z.x, Z.y, Z.z, Z.w};
            const int idx0 = base + e * 4;
#pragma unroll
            for (int k = 0; k < 4; ++k) {
                // FROZEN arithmetic (rel_err 0.0): fma(dz,dz, fma(dx,dx, rn(dy*dy)))
                float dx = __fsub_rn(xv[k], lx);
                float dy = __fsub_rn(yv[k], ly);
                float dz = __fsub_rn(zv[k], lz);
                float d  = __fmaf_rn(dz, dz,
                           __fmaf_rn(dx, dx,
                           __fmul_rn(dy, dy)));
                float m  = fminf(md[j * 4 + k], d);
                md[j * 4 + k] = m;
                // ascending index + strict '>' == first-occurrence argmax
                if (m > bestv) { bestv = m; besti = idx0 + k; }
            }
        }

        // warp argmax (tiebreak: smaller index)
#pragma unroll
        for (int off = 16; off > 0; off >>= 1) {
            float ov = __shfl_down_sync(0xffffffffu, bestv, off);
            int   oi = __shfl_down_sync(0xffffffffu, besti, off);
            if (ov > bestv || (ov == bestv && oi < besti)) { bestv = ov; besti = oi; }
        }
        if (lane == 0) { s_v[wid] = bestv; s_i[wid] = besti; }
        __syncthreads();

        if (wid == 0) {
            const int par = r & 1;
            const unsigned tag = (unsigned)(r + 1) & 0x1FFFu;

            // CTA reduce over 16 warp records (value, idx)
            float v = (lane < 16) ? s_v[lane] : -2.0f;
            int   i = (lane < 16) ? s_i[lane] : 0x7fffffff;
#pragma unroll
            for (int off = 8; off > 0; off >>= 1) {
                float ov = __shfl_down_sync(0xffffffffu, v, off);
                int   oi = __shfl_down_sync(0xffffffffu, i, off);
                if (ov > v || (ov == v && oi < i)) { v = ov; i = oi; }
            }

            unsigned old = 0u;
            if (lane == 0) {
                // own-slice winner coords: L1-resident fetch, pre-publish
                float wx = g_x[b * NP + i];
                float wy = g_y[b * NP + i];
                float wz = g_z[b * NP + i];
                asm volatile("st.global.v4.f32 [%0], {%1,%2,%3,%4};"
                             :: "l"(&S->slotpay[par][c]),
                                "f"(wx), "f"(wy), "f"(wz), "f"(v) : "memory");
                unsigned long long key =
                    ((unsigned long long)__float_as_uint(v) << 32) |
                    ((unsigned long long)tag << 17) | (unsigned)i;
                asm volatile("st.release.gpu.global.b64 [%0], %1;"
                             :: "l"(&S->slotkey[par][c]), "l"(key) : "memory");
                asm volatile("atom.acq_rel.gpu.global.add.u32 %0, [%1], %2;"
                             : "=r"(old) : "l"(&S->cnt), "r"(1u) : "memory");
            }
            old = __shfl_sync(0xffffffffu, old, 0);
            const bool islast = (old == (unsigned)r * CPB + (CPB - 1));

            if (islast) {
                // I am the last arriver: all partials are published & visible.
                unsigned long long k = 0ull;
                float4 pay = make_float4(0.f, 0.f, 0.f, 0.f);
                if (lane < CPB) {
                    asm volatile("ld.global.cg.b64 %0, [%1];"
                                 : "=l"(k) : "l"(&S->slotkey[par][lane]) : "memory");
                    asm volatile("ld.global.cg.v4.f32 {%0,%1,%2,%3}, [%4];"
                                 : "=f"(pay.x), "=f"(pay.y), "=f"(pay.z), "=f"(pay.w)
                                 : "l"(&S->slotpay[par][lane]) : "memory");
                }
                float pv = (lane < CPB) ? __uint_as_float((unsigned)(k >> 32)) : -2.0f;
                int   pi = (lane < CPB) ? (int)((unsigned)k & 0x1FFFFu) : 0x7fffffff;
                int   pl = lane;
#pragma unroll
                for (int off = 8; off > 0; off >>= 1) {
                    float ov = __shfl_xor_sync(0xffffffffu, pv, off);
                    int   oi = __shfl_xor_sync(0xffffffffu, pi, off);
                    int   ol = __shfl_xor_sync(0xffffffffu, pl, off);
                    if (ov > pv || (ov == pv && oi < pi)) { pv = ov; pi = oi; pl = ol; }
                }
                // fetch winner payload from the lane that owns it
                float wx = __shfl_sync(0xffffffffu, pay.x, pl);
                float wy = __shfl_sync(0xffffffffu, pay.y, pl);
                float wz = __shfl_sync(0xffffffffu, pay.z, pl);
                if (lane == 0) {
                    asm volatile("st.global.v4.f32 [%0], {%1,%2,%3,%4};"
                                 :: "l"(&S->respay[par]),
                                    "f"(wx), "f"(wy), "f"(wz), "f"(pv) : "memory");
                    unsigned long long rkey =
                        ((unsigned long long)__float_as_uint(pv) << 32) |
                        ((unsigned long long)tag << 17) | (unsigned)pi;
                    asm volatile("st.release.gpu.global.b64 [%0], %1;"
                                 :: "l"(&S->reskey[par]), "l"(rkey) : "memory");
                    out[(b * NS + r + 1) * 3 + 0] = wx;
                    out[(b * NS + r + 1) * 3 + 1] = wy;
                    out[(b * NS + r + 1) * 3 + 2] = wz;
                    s_win[0] = wx; s_win[1] = wy; s_win[2] = wz;
                }
            } else {
                // poll ONE result key, 32-lane broadcast load
                unsigned long long k;
                do {
                    asm volatile("ld.acquire.gpu.global.b64 %0, [%1];"
                                 : "=l"(k) : "l"(&S->reskey[par]) : "memory");
                } while ((((unsigned)(k >> 17)) & 0x1FFFu) != tag);
                if (lane == 0) {
                    float wx, wy, wz, wv;
                    asm volatile("ld.global.cg.v4.f32 {%0,%1,%2,%3}, [%4];"
                                 : "=f"(wx), "=f"(wy), "=f"(wz), "=f"(wv)
                                 : "l"(&S->respay[par]) : "memory");
                    s_win[0] = wx; s_win[1] = wy; s_win[2] = wz;
                }
            }
        }
        __syncthreads();
        lx = s_win[0]; ly = s_win[1]; lz = s_win[2];
    }
}

extern "C" void kernel_launch(void* const* d_in, const int* in_sizes, int n_in,
                              void* d_out, int out_size) {
    const float* pts = (const float*)d_in[0];
    float* out = (float*)d_out;
    (void)in_sizes; (void)n_in; (void)out_size;

    fps_prep_kernel<<<512, 256>>>(pts);
    fps_main_kernel<<<NB * CPB, NT>>>(out);
}

// round 8
// speedup vs baseline: 1.2379x; 1.2379x over previous
#include <cuda_runtime.h>
#include <cstdint>

// FPS + gather, bit-exact vs JAX/XLA (distance = fma(dz,dz, fma(dx,dx, rn(dy*dy)))).
// B=8, N=131072, S=4096.
//
// R7: coordinates live in REGISTERS (48/thread), loaded once. The compute
// loop does zero memory traffic, so the L1D invalidation caused by GPU-scope
// sync ops (the real bottleneck behind R3/R5/R6's ~3-4us rounds: CCTL.IVALL
// semantics of threadfence/acquire on non-coherent L1) no longer costs
// anything. Winner coords carried from the winning thread's registers through
// all reductions -> no gather. Sync: leader-poller, tagged release/acquire
// records, no atomics, no fences. Compute arithmetic frozen (rel_err 0.0).

#define NB 8
#define NP 131072
#define NS 4096
#define CPB 16                 // CTAs per batch
#define NT 512                 // threads per CTA
#define ROUNDS (NS - 1)
#define PPC (NP / CPB)         // 8192 points per CTA
#define CHUNK 4                // 4 float4 per coord per thread = 16 pts/thread

__device__ float g_x[NB * NP];
__device__ float g_y[NB * NP];
__device__ float g_z[NB * NP];

struct __align__(2048) BSync {
    unsigned long long slotkey[2][CPB];   // [parity][cta] value|tag|idx
    float4             slotpay[2][CPB];   // [parity][cta] x,y,z,v
    unsigned long long reskey[2];         // [parity]
    float4             respay[2];         // [parity] x,y,z,v
};
__device__ BSync g_sync[NB];

__global__ void fps_prep_kernel(const float* __restrict__ pts) {
    if (blockIdx.x == 0 && threadIdx.x < NB) {
        BSync* S = &g_sync[threadIdx.x];
        for (int p = 0; p < 2; ++p) {
            S->reskey[p] = 0ull;                      // tag 0 never matches r+1
            for (int c = 0; c < CPB; ++c) S->slotkey[p][c] = 0ull;
        }
    }
    int i = blockIdx.x * blockDim.x + threadIdx.x;
    int stride = gridDim.x * blockDim.x;
    for (; i < NB * NP; i += stride) {
        g_x[i] = pts[3 * i + 0];
        g_y[i] = pts[3 * i + 1];
        g_z[i] = pts[3 * i + 2];
    }
}

__global__ void __launch_bounds__(NT, 1) fps_main_kernel(float* __restrict__ out) {
    const int b    = blockIdx.x / CPB;
    const int c    = blockIdx.x % CPB;
    const int tid  = threadIdx.x;
    const int lane = tid & 31;
    const int wid  = tid >> 5;
    const int base = c * PPC;
    BSync* __restrict__ S = &g_sync[b];

    // ---- one-time load: 16 points/thread into registers (48 floats) ----
    const float4* __restrict__ x4 = (const float4*)(g_x + b * NP + base);
    const float4* __restrict__ y4 = (const float4*)(g_y + b * NP + base);
    const float4* __restrict__ z4 = (const float4*)(g_z + b * NP + base);

    float px[16], py[16], pz[16], md[16];
#pragma unroll
    for (int j = 0; j < CHUNK; ++j) {
        float4 X = x4[j * NT + tid];
        float4 Y = y4[j * NT + tid];
        float4 Z = z4[j * NT + tid];
        px[j*4+0]=X.x; px[j*4+1]=X.y; px[j*4+2]=X.z; px[j*4+3]=X.w;
        py[j*4+0]=Y.x; py[j*4+1]=Y.y; py[j*4+2]=Y.z; py[j*4+3]=Y.w;
        pz[j*4+0]=Z.x; pz[j*4+1]=Z.y; pz[j*4+2]=Z.z; pz[j*4+3]=Z.w;
    }
#pragma unroll
    for (int i = 0; i < 16; ++i) md[i] = 1e10f;   // BIG

    __shared__ float s_v[16]; __shared__ int s_i[16];
    __shared__ float s_x[16]; __shared__ float s_y[16]; __shared__ float s_z[16];
    __shared__ float s_win[3];

    // selection 0 is always index 0
    float lx = g_x[b * NP + 0];
    float ly = g_y[b * NP + 0];
    float lz = g_z[b * NP + 0];

    if (c == 0 && tid == 0) {
        out[(b * NS + 0) * 3 + 0] = lx;
        out[(b * NS + 0) * 3 + 1] = ly;
        out[(b * NS + 0) * 3 + 2] = lz;
    }

    const int tb = base + tid * 4;   // global idx of this thread's point (j=0,k=0)

    for (int r = 0; r < ROUNDS; ++r) {
        float bestv = -1.0f;
        int   besti = 0x7fffffff;
        float bx = 0.0f, by = 0.0f, bz = 0.0f;

#pragma unroll
        for (int j = 0; j < CHUNK; ++j) {
#pragma unroll
            for (int k = 0; k < 4; ++k) {
                const int t   = j * 4 + k;
                const int idx = tb + j * (NT * 4) + k;
                // FROZEN arithmetic (rel_err 0.0): fma(dz,dz, fma(dx,dx, rn(dy*dy)))
                float dx = __fsub_rn(px[t], lx);
                float dy = __fsub_rn(py[t], ly);
                float dz = __fsub_rn(pz[t], lz);
                float d  = __fmaf_rn(dz, dz,
                           __fmaf_rn(dx, dx,
                           __fmul_rn(dy, dy)));
                float m  = fminf(md[t], d);
                md[t] = m;
                // per-thread ascending idx + strict '>' == first-occurrence argmax
                if (m > bestv) { bestv = m; besti = idx; bx = px[t]; by = py[t]; bz = pz[t]; }
            }
        }

        // warp argmax carrying coords (tiebreak: smaller index)
#pragma unroll
        for (int off = 16; off > 0; off >>= 1) {
            float ov = __shfl_down_sync(0xffffffffu, bestv, off);
            int   oi = __shfl_down_sync(0xffffffffu, besti, off);
            float ox = __shfl_down_sync(0xffffffffu, bx, off);
            float oy = __shfl_down_sync(0xffffffffu, by, off);
            float oz = __shfl_down_sync(0xffffffffu, bz, off);
            if (ov > bestv || (ov == bestv && oi < besti)) {
                bestv = ov; besti = oi; bx = ox; by = oy; bz = oz;
            }
        }
        if (lane == 0) {
            s_v[wid] = bestv; s_i[wid] = besti;
            s_x[wid] = bx; s_y[wid] = by; s_z[wid] = bz;
        }
        __syncthreads();

        if (wid == 0) {
            const int par = r & 1;
            const unsigned tag = (unsigned)(r + 1) & 0x1FFFu;

            // CTA reduce over 16 warp records (bfly: result in all lanes)
            float v = (lane < 16) ? s_v[lane] : -2.0f;
            int   i = (lane < 16) ? s_i[lane] : 0x7fffffff;
            float x = (lane < 16) ? s_x[lane] : 0.0f;
            float y = (lane < 16) ? s_y[lane] : 0.0f;
            float z = (lane < 16) ? s_z[lane] : 0.0f;
#pragma unroll
            for (int off = 8; off > 0; off >>= 1) {
                float ov = __shfl_xor_sync(0xffffffffu, v, off);
                int   oi = __shfl_xor_sync(0xffffffffu, i, off);
                float ox = __shfl_xor_sync(0xffffffffu, x, off);
                float oy = __shfl_xor_sync(0xffffffffu, y, off);
                float oz = __shfl_xor_sync(0xffffffffu, z, off);
                if (ov > v || (ov == v && oi < i)) { v = ov; i = oi; x = ox; y = oy; z = oz; }
            }

            // publish: payload first, then tagged release key
            if (lane == 0) {
                asm volatile("st.global.v4.f32 [%0], {%1,%2,%3,%4};"
                             :: "l"(&S->slotpay[par][c]), "f"(x), "f"(y), "f"(z), "f"(v)
                             : "memory");
                unsigned long long key =
                    ((unsigned long long)__float_as_uint(v) << 32) |
                    ((unsigned long long)tag << 17) | (unsigned)i;
                asm volatile("st.release.gpu.global.b64 [%0], %1;"
                             :: "l"(&S->slotkey[par][c]), "l"(key) : "memory");
            }

            if (c == 0) {
                // leader: poll all 16 slot keys (one lane each) until tagged
                bool got = (lane >= CPB);
                unsigned long long k = 0ull;
                while (!__all_sync(0xffffffffu, got)) {
                    if (!got) {
                        asm volatile("ld.acquire.gpu.global.b64 %0, [%1];"
                                     : "=l"(k) : "l"(&S->slotkey[par][lane]) : "memory");
                        got = ((((unsigned)(k >> 17)) & 0x1FFFu) == tag);
                    }
                }
                float4 pay = make_float4(0.f, 0.f, 0.f, 0.f);
                if (lane < CPB) {
                    asm volatile("ld.global.cg.v4.f32 {%0,%1,%2,%3}, [%4];"
                                 : "=f"(pay.x), "=f"(pay.y), "=f"(pay.z), "=f"(pay.w)
                                 : "l"(&S->slotpay[par][lane]) : "memory");
                }
                float pv = (lane < CPB) ? __uint_as_float((unsigned)(k >> 32)) : -2.0f;
                int   pi = (lane < CPB) ? (int)((unsigned)k & 0x1FFFFu) : 0x7fffffff;
                float qx = pay.x, qy = pay.y, qz = pay.z;
#pragma unroll
                for (int off = 8; off > 0; off >>= 1) {
                    float ov = __shfl_xor_sync(0xffffffffu, pv, off);
                    int   oi = __shfl_xor_sync(0xffffffffu, pi, off);
                    float ox = __shfl_xor_sync(0xffffffffu, qx, off);
                    float oy = __shfl_xor_sync(0xffffffffu, qy, off);
                    float oz = __shfl_xor_sync(0xffffffffu, qz, off);
                    if (ov > pv || (ov == pv && oi < pi)) { pv = ov; pi = oi; qx = ox; qy = oy; qz = oz; }
                }
                if (lane == 0) {
                    asm volatile("st.global.v4.f32 [%0], {%1,%2,%3,%4};"
                                 :: "l"(&S->respay[par]), "f"(qx), "f"(qy), "f"(qz), "f"(pv)
                                 : "memory");
                    unsigned long long rkey =
                        ((unsigned long long)__float_as_uint(pv) << 32) |
                        ((unsigned long long)tag << 17) | (unsigned)pi;
                    asm volatile("st.release.gpu.global.b64 [%0], %1;"
                                 :: "l"(&S->reskey[par]), "l"(rkey) : "memory");
                    out[(b * NS + r + 1) * 3 + 0] = qx;
                    out[(b * NS + r + 1) * 3 + 1] = qy;
                    out[(b * NS + r + 1) * 3 + 2] = qz;
                    s_win[0] = qx; s_win[1] = qy; s_win[2] = qz;
                }
            } else {
                // followers: poll single result key (broadcast load)
                unsigned long long k;
                do {
                    asm volatile("ld.acquire.gpu.global.b64 %0, [%1];"
                                 : "=l"(k) : "l"(&S->reskey[par]) : "memory");
                } while ((((unsigned)(k >> 17)) & 0x1FFFu) != tag);
                if (lane == 0) {
                    float wx, wy, wz, wv;
                    asm volatile("ld.global.cg.v4.f32 {%0,%1,%2,%3}, [%4];"
                                 : "=f"(wx), "=f"(wy), "=f"(wz), "=f"(wv)
                                 : "l"(&S->respay[par]) : "memory");
                    s_win[0] = wx; s_win[1] = wy; s_win[2] = wz;
                }
            }
        }
        __syncthreads();
        lx = s_win[0]; ly = s_win[1]; lz = s_win[2];
    }
}

extern "C" void kernel_launch(void* const* d_in, const int* in_sizes, int n_in,
                              void* d_out, int out_size) {
    const float* pts = (const float*)d_in[0];
    float* out = (float*)d_out;
    (void)in_sizes; (void)n_in; (void)out_size;

    fps_prep_kernel<<<512, 256>>>(pts);
    fps_main_kernel<<<NB * CPB, NT>>>(out);
}

// round 9
// speedup vs baseline: 1.9445x; 1.5709x over previous
#include <cuda_runtime.h>
#include <cstdint>

// FPS + gather, bit-exact vs JAX/XLA (distance = fma(dz,dz, fma(dx,dx, rn(dy*dy)))).
// B=8, N=131072, S=4096.
//
// R8: lean round. Coordinates in registers (48/thread, loaded once from AoS
// g_xyz). In-loop argmax tracks only (v, idx). Reductions on packed u64 keys
// key = vbits<<17 | (0x1FFFF-idx)  (argmax with min-idx tiebreak == u64 max).
// Sync: single-hop all-to-all — each CTA release-stores one tagged slot
// (key<<13 | (r+1)); tags strictly increase so one buffer, no ABA; all CTAs
// poll the 16-slot line (one lane per slot), reduce redundantly, and load
// winner coords from immutable g_xyz. No atomics, no fences, no 2nd hop.

#define NB 8
#define NP 131072
#define NS 4096
#define CPB 16                 // CTAs per batch
#define NT 512                 // threads per CTA
#define ROUNDS (NS - 1)
#define PPC (NP / CPB)         // 8192 points per CTA

__device__ float4 g_xyz[NB * NP];
struct __align__(2048) BSlots { unsigned long long key[CPB]; };
__device__ BSlots g_slots[NB];   // one 128B line per batch, batches on distinct slices

__global__ void fps_prep_kernel(const float* __restrict__ pts) {
    if (blockIdx.x == 0 && threadIdx.x < NB * CPB) {
        g_slots[threadIdx.x / CPB].key[threadIdx.x % CPB] = 0ull;  // tag 0 < 1
    }
    int i = blockIdx.x * blockDim.x + threadIdx.x;
    int stride = gridDim.x * blockDim.x;
    for (; i < NB * NP; i += stride) {
        g_xyz[i] = make_float4(pts[3 * i + 0], pts[3 * i + 1], pts[3 * i + 2], 0.0f);
    }
}

__global__ void __launch_bounds__(NT, 1) fps_main_kernel(float* __restrict__ out) {
    const int b    = blockIdx.x / CPB;
    const int c    = blockIdx.x % CPB;
    const int tid  = threadIdx.x;
    const int lane = tid & 31;
    const int wid  = tid >> 5;
    const int base = c * PPC;
    const float4* __restrict__ P = g_xyz + b * NP;
    unsigned long long* __restrict__ slots = g_slots[b].key;

    // one-time: 16 points/thread into registers
    float px[16], py[16], pz[16], md[16];
#pragma unroll
    for (int j = 0; j < 4; ++j) {
        const int e = j * NT + tid;
#pragma unroll
        for (int k = 0; k < 4; ++k) {
            float4 q = P[base + e * 4 + k];
            px[j * 4 + k] = q.x; py[j * 4 + k] = q.y; pz[j * 4 + k] = q.z;
        }
    }
#pragma unroll
    for (int i = 0; i < 16; ++i) md[i] = 1e10f;   // BIG

    __shared__ unsigned long long s_k[NT / 32];
    __shared__ float s_win[3];

    // selection 0 is always index 0
    float4 p0 = P[0];
    float lx = p0.x, ly = p0.y, lz = p0.z;
    if (c == 0 && tid == 0) {
        out[(b * NS + 0) * 3 + 0] = lx;
        out[(b * NS + 0) * 3 + 1] = ly;
        out[(b * NS + 0) * 3 + 2] = lz;
    }

    const int tb = base + tid * 4;   // global idx of point t=(j=0,k=0)

    for (int r = 0; r < ROUNDS; ++r) {
        float bestv = -1.0f;
        int   besti = 0;

#pragma unroll
        for (int j = 0; j < 4; ++j) {
#pragma unroll
            for (int k = 0; k < 4; ++k) {
                const int t   = j * 4 + k;
                const int idx = tb + j * (NT * 4) + k;
                // FROZEN arithmetic (rel_err 0.0): fma(dz,dz, fma(dx,dx, rn(dy*dy)))
                float dx = __fsub_rn(px[t], lx);
                float dy = __fsub_rn(py[t], ly);
                float dz = __fsub_rn(pz[t], lz);
                float d  = __fmaf_rn(dz, dz,
                           __fmaf_rn(dx, dx,
                           __fmul_rn(dy, dy)));
                float m  = fminf(md[t], d);
                md[t] = m;
                // per-thread ascending idx + strict '>' == first-occurrence argmax
                if (m > bestv) { bestv = m; besti = idx; }
            }
        }

        // pack: max(key) == argmax(v) with min-idx tiebreak (v>=0 -> bits monotonic)
        unsigned long long wkey =
            ((unsigned long long)__float_as_uint(bestv) << 17) |
            (unsigned)(0x1FFFF - besti);

        // warp reduce (down: lane0 gets max)
#pragma unroll
        for (int off = 16; off > 0; off >>= 1) {
            unsigned long long ok = __shfl_down_sync(0xffffffffu, wkey, off);
            if (ok > wkey) wkey = ok;
        }
        if (lane == 0) s_k[wid] = wkey;
        __syncthreads();

        if (wid == 0) {
            const unsigned long long tag = (unsigned long long)(r + 1);  // 13 bits

            // CTA reduce over 16 warp keys
            unsigned long long kk = (lane < 16) ? s_k[lane] : 0ull;
#pragma unroll
            for (int off = 8; off > 0; off >>= 1) {
                unsigned long long ok = __shfl_down_sync(0xffffffffu, kk, off);
                if (ok > kk) kk = ok;
            }
            if (lane == 0) {
                unsigned long long slot = (kk << 13) | tag;
                asm volatile("st.release.gpu.global.b64 [%0], %1;"
                             :: "l"(&slots[c]), "l"(slot) : "memory");
            }

            // single-hop: poll all 16 slots (one lane each) until current tag
            unsigned long long k = 0ull;
            bool got = (lane >= CPB);
            do {
                if (!got) {
                    asm volatile("ld.acquire.gpu.global.b64 %0, [%1];"
                                 : "=l"(k) : "l"(&slots[lane]) : "memory");
                    got = ((k & 0x1FFFull) == tag);
                }
            } while (!__all_sync(0xffffffffu, got));

            unsigned long long k2 = (lane < CPB) ? (k >> 13) : 0ull;
#pragma unroll
            for (int off = 8; off > 0; off >>= 1) {
                unsigned long long ok = __shfl_down_sync(0xffffffffu, k2, off);
                if (ok > k2) k2 = ok;
            }
            if (lane == 0) {
                const int widx = 0x1FFFF - (int)(k2 & 0x1FFFFull);
                float4 w = P[widx];        // immutable -> cache-safe
                s_win[0] = w.x; s_win[1] = w.y; s_win[2] = w.z;
                if (c == 0) {
                    out[(b * NS + r + 1) * 3 + 0] = w.x;
                    out[(b * NS + r + 1) * 3 + 1] = w.y;
                    out[(b * NS + r + 1) * 3 + 2] = w.z;
                }
            }
        }
        __syncthreads();
        lx = s_win[0]; ly = s_win[1]; lz = s_win[2];
    }
}

extern "C" void kernel_launch(void* const* d_in, const int* in_sizes, int n_in,
                              void* d_out, int out_size) {
    const float* pts = (const float*)d_in[0];
    float* out = (float*)d_out;
    (void)in_sizes; (void)n_in; (void)out_size;

    fps_prep_kernel<<<512, 256>>>(pts);
    fps_main_kernel<<<NB * CPB, NT>>>(out);
}